// round 1
// baseline (speedup 1.0000x reference)
#include <cuda_runtime.h>
#include <cstdint>
#include <math.h>

#define NB 8
#define SLEN 2048
#define DMODEL 1024
#define KDIM 1152
#define LMAX 4608
#define NVMAX 4608

// ---------------- device-global scratch (no allocs allowed) ----------------
__device__ int g_src[NB][LMAX];    // >=0: gather text pos; -2: visual (GEMM writes); -1: pad
__device__ int g_meta[NB][LMAX];   // (cid<<1) | vis
__device__ int g_vdst[NB][NVMAX];  // visual token j -> fused row (or -1)
__device__ int g_len[NB];

// ---------------- helpers ----------------
__device__ __forceinline__ uint32_t f2tf32(float x) {
    uint32_t r;
    asm("cvt.rna.tf32.f32 %0, %1;\n" : "=r"(r) : "f"(x));
    return r;
}

__device__ __forceinline__ void mma_tf32(float* d, const uint32_t* a, const uint32_t* b) {
    asm volatile(
        "mma.sync.aligned.m16n8k8.row.col.f32.tf32.tf32.f32 "
        "{%0,%1,%2,%3}, {%4,%5,%6,%7}, {%8,%9}, {%0,%1,%2,%3};\n"
        : "+f"(d[0]), "+f"(d[1]), "+f"(d[2]), "+f"(d[3])
        : "r"(a[0]), "r"(a[1]), "r"(a[2]), "r"(a[3]), "r"(b[0]), "r"(b[1]));
}

__device__ __forceinline__ void cp16(void* smem, const void* gmem) {
    uint32_t s = (uint32_t)__cvta_generic_to_shared(smem);
    asm volatile("cp.async.cg.shared.global [%0], [%1], 16;\n" :: "r"(s), "l"(gmem));
}
#define CP_COMMIT() asm volatile("cp.async.commit_group;\n")
#define CP_WAIT0()  asm volatile("cp.async.wait_group 0;\n")

// ---------------- plan: build interleave indices + chunk metadata ----------
__global__ void plan_kernel(const int* __restrict__ texts,
                            const int* __restrict__ img_id_p,
                            int nvis, int L) {
    int b = blockIdx.x;
    int img_id = *img_id_p;
    const int* t = texts + b * SLEN;
    __shared__ int s_pos[64];
    __shared__ int s_n;
    __shared__ int s_C[65];
    if (threadIdx.x == 0) s_n = 0;
    __syncthreads();
    for (int p = threadIdx.x; p < SLEN; p += blockDim.x)
        if (t[p] == img_id) { int k = atomicAdd(&s_n, 1); if (k < 64) s_pos[k] = p; }
    __syncthreads();
    int n = min(s_n, 64);
    if (threadIdx.x == 0) {
        for (int i = 1; i < n; i++) {               // insertion sort (n tiny)
            int v = s_pos[i]; int j = i - 1;
            while (j >= 0 && s_pos[j] > v) { s_pos[j + 1] = s_pos[j]; j--; }
            s_pos[j + 1] = v;
        }
        int c = 0, start = 0;                        // non-empty text-chunk prefix counts
        for (int i = 0; i < n; i++) { s_C[i] = c; if (s_pos[i] > start) c++; start = s_pos[i] + 1; }
        s_C[n] = c;
    }
    __syncthreads();
    int per = (n > 0) ? (nvis / n) : 0;
    int len = (n > 0) ? (SLEN - n + n * per) : SLEN;
    if (threadIdx.x == 0) g_len[b] = len;
    // text tokens
    for (int p = threadIdx.x; p < SLEN; p += blockDim.x) {
        if (t[p] == img_id) continue;
        int k = 0;
        while (k < n && s_pos[k] < p) k++;
        int fp = (p - k) + k * per;
        g_src[b][fp]  = p;
        g_meta[b][fp] = (s_C[k] + k) << 1;           // text chunk k: cid = C_k + k, vis=0
    }
    // visual tokens
    for (int j = threadIdx.x; j < nvis; j += blockDim.x) {
        int dst = -1;
        if (n > 0 && j < n * per) {
            int i = j / per, r = j - i * per;
            dst = (s_pos[i] - i) + i * per + r;
            g_meta[b][dst] = ((s_C[i + 1] + i) << 1) | 1;  // visual chunk i: cid = C_{i+1}+i, vis=1
            g_src[b][dst]  = -2;
        }
        g_vdst[b][j] = dst;
    }
    // pad
    for (int l = len + threadIdx.x; l < L; l += blockDim.x) { g_src[b][l] = -1; g_meta[b][l] = 0; }
}

// ---------------- text embedding gather + pad zero ----------------
__global__ void __launch_bounds__(256) gather_kernel(const float* __restrict__ emb,
                                                     const int* __restrict__ texts,
                                                     float* __restrict__ out, int L) {
    int l = blockIdx.x;
    int b = blockIdx.y;
    int src = g_src[b][l];
    if (src == -2) return;  // visual row: GEMM epilogue writes it
    float4* dst = reinterpret_cast<float4*>(out + ((size_t)b * L + l) * DMODEL);
    if (src < 0) { dst[threadIdx.x] = make_float4(0.f, 0.f, 0.f, 0.f); return; }
    int tok = texts[b * SLEN + src];
    const float4* s = reinterpret_cast<const float4*>(emb + (size_t)tok * DMODEL);
    dst[threadIdx.x] = s[threadIdx.x];
}

// ---------------- block-causal mask (write-bound) ----------------
__global__ void __launch_bounds__(256) mask_kernel(float* __restrict__ mask, int L) {
    int b  = blockIdx.z;
    int r0 = blockIdx.y * 32;
    int c0 = blockIdx.x * 1024;
    int len = g_len[b];
    __shared__ int s_mc[1024];
    __shared__ int s_mr[32];
    for (int i = threadIdx.x; i < 1024; i += 256) {
        int c = c0 + i;
        s_mc[i] = (c < L) ? g_meta[b][c] : 0;
    }
    if (threadIdx.x < 32) {
        int r = r0 + threadIdx.x;
        s_mr[threadIdx.x] = (r < L) ? g_meta[b][r] : 0;
    }
    __syncthreads();
    int ci = threadIdx.x * 4;
    int c  = c0 + ci;
    if (c >= L) return;  // L % 4 == 0, full float4 is in-bounds
    int cc0 = s_mc[ci]     >> 1;
    int cc1 = s_mc[ci + 1] >> 1;
    int cc2 = s_mc[ci + 2] >> 1;
    int cc3 = s_mc[ci + 3] >> 1;
    bool cv0 = (c + 0) < len, cv1 = (c + 1) < len, cv2 = (c + 2) < len, cv3 = (c + 3) < len;
    size_t base = ((size_t)b * L + r0) * (size_t)L + c;
    int rmax = min(32, L - r0);
    for (int i = 0; i < rmax; i++) {
        int r  = r0 + i;
        int mr = s_mr[i];
        int cr = mr >> 1;
        bool vr = mr & 1;
        bool rv = r < len;
        float4 v;
        v.x = (rv && cv0 && ((cc0 < cr) || (cc0 == cr && (vr || (c + 0) <= r)))) ? 1.f : 0.f;
        v.y = (rv && cv1 && ((cc1 < cr) || (cc1 == cr && (vr || (c + 1) <= r)))) ? 1.f : 0.f;
        v.z = (rv && cv2 && ((cc2 < cr) || (cc2 == cr && (vr || (c + 2) <= r)))) ? 1.f : 0.f;
        v.w = (rv && cv3 && ((cc3 < cr) || (cc3 == cr && (vr || (c + 3) <= r)))) ? 1.f : 0.f;
        *reinterpret_cast<float4*>(mask + base + (size_t)i * L) = v;
    }
}

// ---------------- tf32 projection GEMM, scatter epilogue ----------------
// C[gm, n] = visual[gm, :] @ W[:, n] + bias[n], scattered to fused row g_vdst
#define BM 128
#define BN 128
#define BK 16
#define SA_STRIDE 20
#define SB_STRIDE 132

__global__ void __launch_bounds__(256) gemm_kernel(const float* __restrict__ A,
                                                   const float* __restrict__ W,
                                                   const float* __restrict__ bias,
                                                   float* __restrict__ out,
                                                   int nvis, int L) {
    __shared__ float sA[2][BM * SA_STRIDE];
    __shared__ float sB[2][BK * SB_STRIDE];
    __shared__ float sBias[BN];

    const int tid  = threadIdx.x;
    const int gm0  = blockIdx.y * BM;
    const int nb0  = blockIdx.x * BN;
    const int warp = tid >> 5;
    const int lane = tid & 31;
    const int wm = warp & 1;          // 2 warps along M (64 rows each)
    const int wn = warp >> 1;         // 4 warps along N (32 cols each)
    const int grp = lane >> 2;
    const int qid = lane & 3;

    if (tid < BN) sBias[tid] = bias[nb0 + tid];

    float acc[4][4][4];
    #pragma unroll
    for (int i = 0; i < 4; i++)
        #pragma unroll
        for (int j = 0; j < 4; j++)
            #pragma unroll
            for (int k = 0; k < 4; k++) acc[i][j][k] = 0.f;

    const int KT = KDIM / BK;  // 72

    auto issue_stage = [&](int kt, int st) {
        #pragma unroll
        for (int v = tid; v < 512; v += 256) {       // A: 128 rows x 4 float4
            int row = v >> 2, k4 = v & 3;
            cp16(&sA[st][row * SA_STRIDE + k4 * 4],
                 A + (size_t)(gm0 + row) * KDIM + kt * BK + k4 * 4);
        }
        #pragma unroll
        for (int v = tid; v < 512; v += 256) {       // B: 16 k-rows x 32 float4
            int kr = v >> 5, n4 = v & 31;
            cp16(&sB[st][kr * SB_STRIDE + n4 * 4],
                 W + (size_t)(kt * BK + kr) * DMODEL + nb0 + n4 * 4);
        }
        CP_COMMIT();
    };

    issue_stage(0, 0);

    for (int kt = 0; kt < KT; kt++) {
        int st = kt & 1;
        CP_WAIT0();
        __syncthreads();
        if (kt + 1 < KT) issue_stage(kt + 1, (kt + 1) & 1);

        #pragma unroll
        for (int ks = 0; ks < 2; ks++) {
            int kb = ks * 8;
            uint32_t af[4][4];
            uint32_t bf[4][2];
            #pragma unroll
            for (int mt = 0; mt < 4; mt++) {
                int r0i = (wm * 64 + mt * 16 + grp) * SA_STRIDE + kb + qid;
                int r1i = r0i + 8 * SA_STRIDE;
                af[mt][0] = f2tf32(sA[st][r0i]);
                af[mt][1] = f2tf32(sA[st][r1i]);
                af[mt][2] = f2tf32(sA[st][r0i + 4]);
                af[mt][3] = f2tf32(sA[st][r1i + 4]);
            }
            #pragma unroll
            for (int nt = 0; nt < 4; nt++) {
                int col = wn * 32 + nt * 8 + grp;
                bf[nt][0] = f2tf32(sB[st][(kb + qid) * SB_STRIDE + col]);
                bf[nt][1] = f2tf32(sB[st][(kb + qid + 4) * SB_STRIDE + col]);
            }
            #pragma unroll
            for (int mt = 0; mt < 4; mt++)
                #pragma unroll
                for (int nt = 0; nt < 4; nt++)
                    mma_tf32(acc[mt][nt], af[mt], bf[nt]);
        }
        __syncthreads();
    }

    // epilogue: scatter rows to fused positions
    #pragma unroll
    for (int mt = 0; mt < 4; mt++) {
        int gmA = gm0 + wm * 64 + mt * 16 + grp;
        #pragma unroll
        for (int half = 0; half < 2; half++) {
            int gm = gmA + half * 8;
            int bb = gm / nvis;
            int j  = gm - bb * nvis;
            int dst = g_vdst[bb][j];
            if (dst < 0) continue;
            float* orow = out + ((size_t)bb * L + dst) * DMODEL + nb0;
            #pragma unroll
            for (int nt = 0; nt < 4; nt++) {
                int col = wn * 32 + nt * 8 + qid * 2;
                float2 v;
                v.x = acc[mt][nt][half * 2 + 0] + sBias[col];
                v.y = acc[mt][nt][half * 2 + 1] + sBias[col + 1];
                *reinterpret_cast<float2*>(orow + col) = v;
            }
        }
    }
}

// ---------------- launch ----------------
extern "C" void kernel_launch(void* const* d_in, const int* in_sizes, int n_in,
                              void* d_out, int out_size) {
    const float* visual = (const float*)d_in[0];
    const float* emb    = (const float*)d_in[1];
    const float* Wp     = (const float*)d_in[2];
    const float* bp     = (const float*)d_in[3];
    const int*   texts  = (const int*)d_in[4];
    const int*   img_id = (const int*)d_in[5];

    const int D    = in_sizes[3];                 // 1024
    const int DV   = in_sizes[2] / D;             // 1152
    const int nvis = in_sizes[0] / (NB * DV);     // 2304
    (void)D; (void)n_in;

    // Solve B*L*D + B*L*L == out_size  ->  L
    double osB = (double)out_size / (double)NB;
    int L = (int)((-(double)DMODEL + sqrt((double)DMODEL * DMODEL + 4.0 * osB)) / 2.0 + 0.5);

    float* out_fused = (float*)d_out;
    float* out_mask  = (float*)d_out + (size_t)NB * L * DMODEL;

    plan_kernel<<<NB, 256>>>(texts, img_id, nvis, L);

    gather_kernel<<<dim3(L, NB), 256>>>(emb, texts, out_fused, L);

    dim3 mg((L + 1023) / 1024, (L + 31) / 32, NB);
    mask_kernel<<<mg, 256>>>(out_mask, L);

    int M = NB * nvis;  // 18432, divisible by BM
    gemm_kernel<<<dim3(DMODEL / BN, M / BM), 256>>>(visual, Wp, bp, out_fused, nvis, L);
}

// round 3
// speedup vs baseline: 1.5075x; 1.5075x over previous
#include <cuda_runtime.h>
#include <cuda_fp16.h>
#include <cstdint>
#include <math.h>

#define NB 8
#define SLEN 2048
#define DMODEL 1024
#define KDIM 1152
#define LMAX 4608
#define NVMAX 4608
#define MTOT (NB * 2304)   // 18432

// ---------------- device-global scratch (no allocs allowed) ----------------
__device__ int g_src[NB][LMAX];    // >=0: gather text pos; -2: visual (GEMM writes); -1: pad
__device__ int g_meta[NB][LMAX];   // (cid<<1) | vis
__device__ int g_vdst[NB][NVMAX];  // visual token j -> fused row (or -1)
__device__ int g_len[NB];
__device__ __half g_Ah[(size_t)MTOT * KDIM];     // visual features as fp16 (42.5MB)
__device__ __half g_Wh[(size_t)DMODEL * KDIM];   // W transposed to [N, K] fp16 (2.4MB)

// ---------------- PTX helpers ----------------
__device__ __forceinline__ uint32_t smem_u32(const void* p) {
    uint32_t a;
    asm("{ .reg .u64 t; cvta.to.shared.u64 t, %1; cvt.u32.u64 %0, t; }" : "=r"(a) : "l"(p));
    return a;
}
__device__ __forceinline__ void cp16(void* smem, const void* gmem) {
    uint32_t s = smem_u32(smem);
    asm volatile("cp.async.cg.shared.global [%0], [%1], 16;\n" :: "r"(s), "l"(gmem));
}
#define CP_COMMIT() asm volatile("cp.async.commit_group;\n")
#define CP_WAIT1()  asm volatile("cp.async.wait_group 1;\n")

#define LDSM_X4(r, addr) \
    asm volatile("ldmatrix.sync.aligned.m8n8.x4.shared.b16 {%0,%1,%2,%3}, [%4];" \
        : "=r"((r)[0]), "=r"((r)[1]), "=r"((r)[2]), "=r"((r)[3]) : "r"(addr))

__device__ __forceinline__ void mma_f16(float* d, const uint32_t* a, const uint32_t* b) {
    asm volatile(
        "mma.sync.aligned.m16n8k16.row.col.f32.f16.f16.f32 "
        "{%0,%1,%2,%3}, {%4,%5,%6,%7}, {%8,%9}, {%0,%1,%2,%3};\n"
        : "+f"(d[0]), "+f"(d[1]), "+f"(d[2]), "+f"(d[3])
        : "r"(a[0]), "r"(a[1]), "r"(a[2]), "r"(a[3]), "r"(b[0]), "r"(b[1]));
}

// ---------------- plan: build interleave indices + chunk metadata ----------
__global__ void plan_kernel(const int* __restrict__ texts,
                            const int* __restrict__ img_id_p,
                            int nvis, int L) {
    int b = blockIdx.x;
    int img_id = *img_id_p;
    const int* t = texts + b * SLEN;
    __shared__ int s_pos[64];
    __shared__ int s_n;
    __shared__ int s_C[65];
    if (threadIdx.x == 0) s_n = 0;
    __syncthreads();
    for (int p = threadIdx.x; p < SLEN; p += blockDim.x)
        if (t[p] == img_id) { int k = atomicAdd(&s_n, 1); if (k < 64) s_pos[k] = p; }
    __syncthreads();
    int n = min(s_n, 64);
    if (threadIdx.x == 0) {
        for (int i = 1; i < n; i++) {
            int v = s_pos[i]; int j = i - 1;
            while (j >= 0 && s_pos[j] > v) { s_pos[j + 1] = s_pos[j]; j--; }
            s_pos[j + 1] = v;
        }
        int c = 0, start = 0;
        for (int i = 0; i < n; i++) { s_C[i] = c; if (s_pos[i] > start) c++; start = s_pos[i] + 1; }
        s_C[n] = c;
    }
    __syncthreads();
    int per = (n > 0) ? (nvis / n) : 0;
    int len = (n > 0) ? (SLEN - n + n * per) : SLEN;
    if (threadIdx.x == 0) g_len[b] = len;
    for (int p = threadIdx.x; p < SLEN; p += blockDim.x) {
        if (t[p] == img_id) continue;
        int k = 0;
        while (k < n && s_pos[k] < p) k++;
        int fp = (p - k) + k * per;
        g_src[b][fp]  = p;
        g_meta[b][fp] = (s_C[k] + k) << 1;
    }
    for (int j = threadIdx.x; j < nvis; j += blockDim.x) {
        int dst = -1;
        if (n > 0 && j < n * per) {
            int i = j / per, r = j - i * per;
            dst = (s_pos[i] - i) + i * per + r;
            g_meta[b][dst] = ((s_C[i + 1] + i) << 1) | 1;
            g_src[b][dst]  = -2;
        }
        g_vdst[b][j] = dst;
    }
    for (int l = len + threadIdx.x; l < L; l += blockDim.x) { g_src[b][l] = -1; g_meta[b][l] = 0; }
}

// ---------------- convert A (visual) fp32 -> fp16 ----------------
__global__ void __launch_bounds__(256) conv_a_kernel(const float* __restrict__ A, int n4) {
    int i = blockIdx.x * 256 + threadIdx.x;
    if (i >= n4) return;
    float4 v = reinterpret_cast<const float4*>(A)[i];
    __half2* dst = reinterpret_cast<__half2*>(g_Ah) + i * 2;
    dst[0] = __floats2half2_rn(v.x, v.y);
    dst[1] = __floats2half2_rn(v.z, v.w);
}

// ---------------- prep: transpose W -> g_Wh[N][K] fp16 ----------------
__global__ void __launch_bounds__(256) prep_w_kernel(const float* __restrict__ W) {
    __shared__ float t[32][33];
    int k0 = blockIdx.x * 32, n0 = blockIdx.y * 32;
    int tx = threadIdx.x, ty = threadIdx.y;
    #pragma unroll
    for (int i = ty; i < 32; i += 8)
        t[i][tx] = W[(size_t)(k0 + i) * DMODEL + n0 + tx];
    __syncthreads();
    #pragma unroll
    for (int i = ty; i < 32; i += 8)
        g_Wh[(size_t)(n0 + i) * KDIM + k0 + tx] = __float2half_rn(t[tx][i]);
}

// ---------------- text embedding gather + pad zero ----------------
__global__ void __launch_bounds__(256) gather_kernel(const float* __restrict__ emb,
                                                     const int* __restrict__ texts,
                                                     float* __restrict__ out, int L) {
    int l = blockIdx.x;
    int b = blockIdx.y;
    int src = g_src[b][l];
    if (src == -2) return;
    float4* dst = reinterpret_cast<float4*>(out + ((size_t)b * L + l) * DMODEL);
    if (src < 0) { dst[threadIdx.x] = make_float4(0.f, 0.f, 0.f, 0.f); return; }
    int tok = texts[b * SLEN + src];
    const float4* s = reinterpret_cast<const float4*>(emb + (size_t)tok * DMODEL);
    dst[threadIdx.x] = s[threadIdx.x];
}

// ---------------- block-causal mask (write-bound) ----------------
__global__ void __launch_bounds__(256) mask_kernel(float* __restrict__ mask, int L) {
    int b  = blockIdx.z;
    int r0 = blockIdx.y * 32;
    int c0 = blockIdx.x * 1024;
    int len = g_len[b];
    __shared__ int s_mc[1024];
    __shared__ int s_mr[32];
    for (int i = threadIdx.x; i < 1024; i += 256) {
        int c = c0 + i;
        s_mc[i] = (c < L) ? g_meta[b][c] : 0;
    }
    if (threadIdx.x < 32) {
        int r = r0 + threadIdx.x;
        s_mr[threadIdx.x] = (r < L) ? g_meta[b][r] : 0;
    }
    __syncthreads();
    int ci = threadIdx.x * 4;
    int c  = c0 + ci;
    if (c >= L) return;
    int cc0 = s_mc[ci] >> 1, cc1 = s_mc[ci + 1] >> 1, cc2 = s_mc[ci + 2] >> 1, cc3 = s_mc[ci + 3] >> 1;
    bool cv0 = (c + 0) < len, cv1 = (c + 1) < len, cv2 = (c + 2) < len, cv3 = (c + 3) < len;
    size_t base = ((size_t)b * L + r0) * (size_t)L + c;
    int rmax = min(32, L - r0);
    for (int i = 0; i < rmax; i++) {
        int r  = r0 + i;
        int mr = s_mr[i];
        int cr = mr >> 1;
        bool vr = mr & 1;
        bool rv = r < len;
        float4 v;
        v.x = (rv && cv0 && ((cc0 < cr) || (cc0 == cr && (vr || (c + 0) <= r)))) ? 1.f : 0.f;
        v.y = (rv && cv1 && ((cc1 < cr) || (cc1 == cr && (vr || (c + 1) <= r)))) ? 1.f : 0.f;
        v.z = (rv && cv2 && ((cc2 < cr) || (cc2 == cr && (vr || (c + 2) <= r)))) ? 1.f : 0.f;
        v.w = (rv && cv3 && ((cc3 < cr) || (cc3 == cr && (vr || (c + 3) <= r)))) ? 1.f : 0.f;
        *reinterpret_cast<float4*>(mask + base + (size_t)i * L) = v;
    }
}

// ---------------- fp16 mma GEMM: 128x128x32 tiles, cp.async 3-stage --------
// C[gm,n] = A[gm,:] @ Wh[n,:]^T + bias[n], scattered to fused row g_vdst
#define GBM 128
#define GBN 128
#define GBK 32
#define STR_B 80                     // bytes per smem row (40 halves, conflict-free for ldmatrix)
#define ATILE_B (128 * STR_B)        // 10240
#define STAGE_B (2 * ATILE_B)        // 20480
#define NSTG 3
#define GEMM_SMEM (NSTG * STAGE_B + 512)

__global__ void __launch_bounds__(256, 2) gemm_h_kernel(const float* __restrict__ bias,
                                                        float* __restrict__ out,
                                                        int nvis, int L) {
    extern __shared__ char smem[];
    float* sBias = reinterpret_cast<float*>(smem + NSTG * STAGE_B);

    const int tid = threadIdx.x, wid = tid >> 5, lane = tid & 31;
    const int gm0 = blockIdx.y * GBM;
    const int nb0 = blockIdx.x * GBN;
    const int wm = wid & 1;       // 2 warps along M (64 rows)
    const int wn = wid >> 1;      // 4 warps along N (32 cols)
    const int grp = lane >> 2;
    const int qid = lane & 3;

    if (tid < 128) sBias[tid] = bias[nb0 + tid];

    const __half* Ag = g_Ah + (size_t)gm0 * KDIM;
    const __half* Bg = g_Wh + (size_t)nb0 * KDIM;

    float acc[4][4][4];
    #pragma unroll
    for (int i = 0; i < 4; i++)
        #pragma unroll
        for (int j = 0; j < 4; j++)
            #pragma unroll
            for (int k = 0; k < 4; k++) acc[i][j][k] = 0.f;

    const int KT = KDIM / GBK;  // 36

    auto issue = [&](int kt) {
        int s = kt % NSTG;
        char* dA = smem + s * STAGE_B;
        char* dB = dA + ATILE_B;
        #pragma unroll
        for (int v = tid; v < 512; v += 256) {
            int row = v >> 2, c = v & 3;
            cp16(dA + row * STR_B + c * 16, Ag + (size_t)row * KDIM + kt * GBK + c * 8);
        }
        #pragma unroll
        for (int v = tid; v < 512; v += 256) {
            int row = v >> 2, c = v & 3;
            cp16(dB + row * STR_B + c * 16, Bg + (size_t)row * KDIM + kt * GBK + c * 8);
        }
        CP_COMMIT();
    };

    issue(0);
    issue(1);

    // ldmatrix source addresses (per-thread constants except stage/ks offsets)
    const int a_row = wm * 64 + (lane & 15);
    const int a_colb = (lane >> 4) * 16;              // bytes
    const int b_row0 = wn * 32 + (lane & 7) + ((lane >> 4) & 1) * 8;
    const int b_colb = ((lane >> 3) & 1) * 16;        // bytes

    for (int kt = 0; kt < KT; kt++) {
        CP_WAIT1();
        __syncthreads();
        if (kt + 2 < KT) issue(kt + 2);

        char* sA = smem + (kt % NSTG) * STAGE_B;
        char* sB = sA + ATILE_B;
        #pragma unroll
        for (int ks = 0; ks < 2; ks++) {
            uint32_t a[4][4], bfr[2][4];
            #pragma unroll
            for (int mt = 0; mt < 4; mt++) {
                uint32_t addr = smem_u32(sA + (a_row + mt * 16) * STR_B + ks * 32 + a_colb);
                LDSM_X4(a[mt], addr);
            }
            #pragma unroll
            for (int p = 0; p < 2; p++) {
                uint32_t addr = smem_u32(sB + (b_row0 + p * 16) * STR_B + ks * 32 + b_colb);
                LDSM_X4(bfr[p], addr);
            }
            #pragma unroll
            for (int mt = 0; mt < 4; mt++) {
                #pragma unroll
                for (int nt = 0; nt < 4; nt++)
                    mma_f16(acc[mt][nt], a[mt], &bfr[nt >> 1][(nt & 1) * 2]);
            }
        }
        __syncthreads();
    }

    // epilogue: scatter rows to fused positions
    #pragma unroll
    for (int mt = 0; mt < 4; mt++) {
        int gmA = gm0 + wm * 64 + mt * 16 + grp;
        #pragma unroll
        for (int half = 0; half < 2; half++) {
            int gm = gmA + half * 8;
            int bb = gm / nvis;
            int j  = gm - bb * nvis;
            int dst = g_vdst[bb][j];
            if (dst < 0) continue;
            float* orow = out + ((size_t)bb * L + dst) * DMODEL + nb0;
            #pragma unroll
            for (int nt = 0; nt < 4; nt++) {
                int col = wn * 32 + nt * 8 + qid * 2;
                float2 v;
                v.x = acc[mt][nt][half * 2 + 0] + sBias[col];
                v.y = acc[mt][nt][half * 2 + 1] + sBias[col + 1];
                *reinterpret_cast<float2*>(orow + col) = v;
            }
        }
    }
}

// ---------------- host launch ----------------
extern "C" void kernel_launch(void* const* d_in, const int* in_sizes, int n_in,
                              void* d_out, int out_size) {
    const float* visual = (const float*)d_in[0];
    const float* emb    = (const float*)d_in[1];
    const float* Wp     = (const float*)d_in[2];
    const float* bp     = (const float*)d_in[3];
    const int*   texts  = (const int*)d_in[4];
    const int*   img_id = (const int*)d_in[5];

    const int D    = in_sizes[3];               // 1024
    const int DV   = in_sizes[2] / D;           // 1152
    const int nvis = in_sizes[0] / (NB * DV);   // 2304
    (void)n_in;

    double osB = (double)out_size / (double)NB;
    int L = (int)((-(double)DMODEL + sqrt((double)DMODEL * DMODEL + 4.0 * osB)) / 2.0 + 0.5);

    float* out_fused = (float*)d_out;
    float* out_mask  = (float*)d_out + (size_t)NB * L * DMODEL;
    const int Mtot = NB * nvis;  // 18432

    cudaFuncSetAttribute(gemm_h_kernel, cudaFuncAttributeMaxDynamicSharedMemorySize, GEMM_SMEM);

    plan_kernel<<<NB, 256>>>(texts, img_id, nvis, L);

    int n4 = Mtot * KDIM / 4;
    conv_a_kernel<<<(n4 + 255) / 256, 256>>>(visual, n4);

    prep_w_kernel<<<dim3(KDIM / 32, DMODEL / 32), dim3(32, 8)>>>(Wp);

    gather_kernel<<<dim3(L, NB), 256>>>(emb, texts, out_fused, L);

    dim3 mg((L + 1023) / 1024, (L + 31) / 32, NB);
    mask_kernel<<<mg, 256>>>(out_mask, L);

    gemm_h_kernel<<<dim3(DMODEL / GBN, Mtot / GBM), 256, GEMM_SMEM>>>(bp, out_fused, nvis, L);
}

// round 4
// speedup vs baseline: 1.6802x; 1.1146x over previous
#include <cuda_runtime.h>
#include <cuda_fp16.h>
#include <cstdint>
#include <math.h>

#define NB 8
#define SLEN 2048
#define DMODEL 1024
#define KDIM 1152
#define LMAX 4608
#define NVMAX 4608
#define MTOT (NB * 2304)   // 18432

// ---------------- device-global scratch (no allocs allowed) ----------------
__device__ int g_src[NB][LMAX];    // >=0: gather text pos; -2: visual (GEMM writes); -1: pad
__device__ int g_X[NB][LMAX];      // mask row r: ones for c < X_r, zeros after
__device__ int g_vdst[NB][NVMAX];  // visual token j -> fused row (or -1)
__device__ __half g_Ah[(size_t)MTOT * KDIM];     // visual features as fp16 (42.5MB)
__device__ __half g_Wh[(size_t)DMODEL * KDIM];   // W transposed to [N, K] fp16 (2.4MB)

// ---------------- PTX helpers ----------------
__device__ __forceinline__ uint32_t smem_u32(const void* p) {
    uint32_t a;
    asm("{ .reg .u64 t; cvta.to.shared.u64 t, %1; cvt.u32.u64 %0, t; }" : "=r"(a) : "l"(p));
    return a;
}
__device__ __forceinline__ void cp16(void* smem, const void* gmem) {
    uint32_t s = smem_u32(smem);
    asm volatile("cp.async.cg.shared.global [%0], [%1], 16;\n" :: "r"(s), "l"(gmem));
}
#define CP_COMMIT() asm volatile("cp.async.commit_group;\n")
#define CP_WAIT2()  asm volatile("cp.async.wait_group 2;\n")

#define LDSM_X4(r, addr) \
    asm volatile("ldmatrix.sync.aligned.m8n8.x4.shared.b16 {%0,%1,%2,%3}, [%4];" \
        : "=r"((r)[0]), "=r"((r)[1]), "=r"((r)[2]), "=r"((r)[3]) : "r"(addr))

__device__ __forceinline__ void mma_f16(float* d, const uint32_t* a, const uint32_t* b) {
    asm volatile(
        "mma.sync.aligned.m16n8k16.row.col.f32.f16.f16.f32 "
        "{%0,%1,%2,%3}, {%4,%5,%6,%7}, {%8,%9}, {%0,%1,%2,%3};\n"
        : "+f"(d[0]), "+f"(d[1]), "+f"(d[2]), "+f"(d[3])
        : "r"(a[0]), "r"(a[1]), "r"(a[2]), "r"(a[3]), "r"(b[0]), "r"(b[1]));
}

// ---------------- plan: build interleave indices + mask prefix lengths -----
__global__ void plan_kernel(const int* __restrict__ texts,
                            const int* __restrict__ img_id_p,
                            int nvis, int L) {
    int b = blockIdx.x;
    int img_id = *img_id_p;
    const int* t = texts + b * SLEN;
    __shared__ int s_pos[64];
    __shared__ int s_n;
    if (threadIdx.x == 0) s_n = 0;
    __syncthreads();
    for (int p = threadIdx.x; p < SLEN; p += blockDim.x)
        if (t[p] == img_id) { int k = atomicAdd(&s_n, 1); if (k < 64) s_pos[k] = p; }
    __syncthreads();
    int n = min(s_n, 64);
    if (threadIdx.x == 0) {
        for (int i = 1; i < n; i++) {
            int v = s_pos[i]; int j = i - 1;
            while (j >= 0 && s_pos[j] > v) { s_pos[j + 1] = s_pos[j]; j--; }
            s_pos[j + 1] = v;
        }
    }
    __syncthreads();
    int per = (n > 0) ? (nvis / n) : 0;
    int len = (n > 0) ? (SLEN - n + n * per) : SLEN;
    // text tokens: causal within own chunk + all earlier -> prefix = fp+1
    for (int p = threadIdx.x; p < SLEN; p += blockDim.x) {
        if (t[p] == img_id) continue;
        int k = 0;
        while (k < n && s_pos[k] < p) k++;
        int fp = (p - k) + k * per;
        g_src[b][fp] = p;
        g_X[b][fp]   = fp + 1;
    }
    // visual tokens: bidirectional within chunk -> prefix = end of own chunk
    for (int j = threadIdx.x; j < nvis; j += blockDim.x) {
        int dst = -1;
        if (n > 0 && j < n * per) {
            int i = j / per;
            dst = (s_pos[i] - i) + i * per + (j - i * per);
            g_src[b][dst] = -2;
            g_X[b][dst]   = (s_pos[i] - i) + (i + 1) * per;
        }
        g_vdst[b][j] = dst;
    }
    // padding rows
    for (int l = len + threadIdx.x; l < L; l += blockDim.x) { g_src[b][l] = -1; g_X[b][l] = 0; }
}

// ---------------- convert A (visual) fp32 -> fp16 ----------------
__global__ void __launch_bounds__(256) conv_a_kernel(const float* __restrict__ A, int n8) {
    int i = blockIdx.x * 256 + threadIdx.x;
    if (i >= n8) return;
    const float4* src = reinterpret_cast<const float4*>(A) + (size_t)i * 2;
    float4 v0 = src[0], v1 = src[1];
    float4 o;
    o.x = __uint_as_float((uint32_t)__half_as_ushort(__float2half_rn(v0.x)) |
                          ((uint32_t)__half_as_ushort(__float2half_rn(v0.y)) << 16));
    o.y = __uint_as_float((uint32_t)__half_as_ushort(__float2half_rn(v0.z)) |
                          ((uint32_t)__half_as_ushort(__float2half_rn(v0.w)) << 16));
    o.z = __uint_as_float((uint32_t)__half_as_ushort(__float2half_rn(v1.x)) |
                          ((uint32_t)__half_as_ushort(__float2half_rn(v1.y)) << 16));
    o.w = __uint_as_float((uint32_t)__half_as_ushort(__float2half_rn(v1.z)) |
                          ((uint32_t)__half_as_ushort(__float2half_rn(v1.w)) << 16));
    __stcs(reinterpret_cast<float4*>(g_Ah) + i, o);
}

// ---------------- prep: transpose W -> g_Wh[N][K] fp16 ----------------
__global__ void __launch_bounds__(256) prep_w_kernel(const float* __restrict__ W) {
    __shared__ float t[32][33];
    int k0 = blockIdx.x * 32, n0 = blockIdx.y * 32;
    int tx = threadIdx.x, ty = threadIdx.y;
    #pragma unroll
    for (int i = ty; i < 32; i += 8)
        t[i][tx] = W[(size_t)(k0 + i) * DMODEL + n0 + tx];
    __syncthreads();
    #pragma unroll
    for (int i = ty; i < 32; i += 8)
        g_Wh[(size_t)(n0 + i) * KDIM + k0 + tx] = __float2half_rn(t[tx][i]);
}

// ---------------- text embedding gather (1 row/warp, MLP 8) ----------------
__global__ void __launch_bounds__(256) gather_kernel(const float* __restrict__ emb,
                                                     const int* __restrict__ texts,
                                                     float* __restrict__ out, int L) {
    int row = blockIdx.x * 8 + (threadIdx.x >> 5);
    int lane = threadIdx.x & 31;
    int b = row / L, l = row - b * L;
    if (b >= NB) return;
    int src = g_src[b][l];
    if (src == -2) return;  // visual row: GEMM epilogue writes it
    float4* dst = reinterpret_cast<float4*>(out + ((size_t)b * L + l) * DMODEL);
    if (src < 0) {
        float4 z = make_float4(0.f, 0.f, 0.f, 0.f);
        #pragma unroll
        for (int k = 0; k < 8; k++) __stcs(dst + lane + k * 32, z);
        return;
    }
    int tok = texts[b * SLEN + src];
    const float4* s = reinterpret_cast<const float4*>(emb + (size_t)tok * DMODEL);
    float4 v[8];
    #pragma unroll
    for (int k = 0; k < 8; k++) v[k] = s[lane + k * 32];
    #pragma unroll
    for (int k = 0; k < 8; k++) __stcs(dst + lane + k * 32, v[k]);
}

// ---------------- mask: prefix-of-ones rows, pure streaming stores ---------
__global__ void __launch_bounds__(256) mask_kernel(float* __restrict__ mask, int L) {
    int b  = blockIdx.z;
    int r0 = blockIdx.y * 16;
    int c  = blockIdx.x * 1024 + threadIdx.x * 4;
    __shared__ int s_X[16];
    if (threadIdx.x < 16) {
        int r = r0 + threadIdx.x;
        s_X[threadIdx.x] = (r < L) ? g_X[b][r] : 0;
    }
    __syncthreads();
    if (c >= L) return;  // L % 4 == 0
    size_t base = ((size_t)b * L + r0) * (size_t)L + c;
    int rmax = min(16, L - r0);
    #pragma unroll 4
    for (int i = 0; i < rmax; i++) {
        int X = s_X[i];
        float4 v;
        v.x = (c + 0 < X) ? 1.f : 0.f;
        v.y = (c + 1 < X) ? 1.f : 0.f;
        v.z = (c + 2 < X) ? 1.f : 0.f;
        v.w = (c + 3 < X) ? 1.f : 0.f;
        __stcs(reinterpret_cast<float4*>(mask + base + (size_t)i * L), v);
    }
}

// ---------------- fp16 mma GEMM: 128x128x32 tiles, cp.async 4-stage --------
#define GBM 128
#define GBN 128
#define GBK 32
#define STR_B 80                     // bytes per smem row (40 halves, ldmatrix conflict-free)
#define ATILE_B (128 * STR_B)        // 10240
#define STAGE_B (2 * ATILE_B)        // 20480
#define NSTG 4
#define GEMM_SMEM (NSTG * STAGE_B + 512)

__global__ void __launch_bounds__(256, 2) gemm_h_kernel(const float* __restrict__ bias,
                                                        float* __restrict__ out,
                                                        int nvis, int L) {
    extern __shared__ char smem[];
    float* sBias = reinterpret_cast<float*>(smem + NSTG * STAGE_B);

    const int tid = threadIdx.x, wid = tid >> 5, lane = tid & 31;
    const int gm0 = blockIdx.y * GBM;
    const int nb0 = blockIdx.x * GBN;
    const int wm = wid & 1;       // 2 warps along M (64 rows)
    const int wn = wid >> 1;      // 4 warps along N (32 cols)
    const int grp = lane >> 2;
    const int qid = lane & 3;

    if (tid < 128) sBias[tid] = bias[nb0 + tid];

    const __half* Ag = g_Ah + (size_t)gm0 * KDIM;
    const __half* Bg = g_Wh + (size_t)nb0 * KDIM;

    float acc[4][4][4];
    #pragma unroll
    for (int i = 0; i < 4; i++)
        #pragma unroll
        for (int j = 0; j < 4; j++)
            #pragma unroll
            for (int k = 0; k < 4; k++) acc[i][j][k] = 0.f;

    const int KT = KDIM / GBK;  // 36

    auto issue = [&](int kt) {
        int s = kt % NSTG;
        char* dA = smem + s * STAGE_B;
        char* dB = dA + ATILE_B;
        #pragma unroll
        for (int v = tid; v < 512; v += 256) {
            int row = v >> 2, c = v & 3;
            cp16(dA + row * STR_B + c * 16, Ag + (size_t)row * KDIM + kt * GBK + c * 8);
        }
        #pragma unroll
        for (int v = tid; v < 512; v += 256) {
            int row = v >> 2, c = v & 3;
            cp16(dB + row * STR_B + c * 16, Bg + (size_t)row * KDIM + kt * GBK + c * 8);
        }
        CP_COMMIT();
    };

    issue(0);
    issue(1);
    issue(2);

    const int a_row = wm * 64 + (lane & 15);
    const int a_colb = (lane >> 4) * 16;
    const int b_row0 = wn * 32 + (lane & 7) + ((lane >> 4) & 1) * 8;
    const int b_colb = ((lane >> 3) & 1) * 16;

    for (int kt = 0; kt < KT; kt++) {
        CP_WAIT2();
        __syncthreads();
        if (kt + 3 < KT) issue(kt + 3);

        char* sA = smem + (kt % NSTG) * STAGE_B;
        char* sB = sA + ATILE_B;
        #pragma unroll
        for (int ks = 0; ks < 2; ks++) {
            uint32_t a[4][4], bfr[2][4];
            #pragma unroll
            for (int mt = 0; mt < 4; mt++) {
                uint32_t addr = smem_u32(sA + (a_row + mt * 16) * STR_B + ks * 32 + a_colb);
                LDSM_X4(a[mt], addr);
            }
            #pragma unroll
            for (int p = 0; p < 2; p++) {
                uint32_t addr = smem_u32(sB + (b_row0 + p * 16) * STR_B + ks * 32 + b_colb);
                LDSM_X4(bfr[p], addr);
            }
            #pragma unroll
            for (int mt = 0; mt < 4; mt++) {
                #pragma unroll
                for (int nt = 0; nt < 4; nt++)
                    mma_f16(acc[mt][nt], a[mt], &bfr[nt >> 1][(nt & 1) * 2]);
            }
        }
        __syncthreads();
    }

    // epilogue: scatter rows to fused positions
    #pragma unroll
    for (int mt = 0; mt < 4; mt++) {
        int gmA = gm0 + wm * 64 + mt * 16 + grp;
        #pragma unroll
        for (int half = 0; half < 2; half++) {
            int gm = gmA + half * 8;
            int bb = gm / nvis;
            int j  = gm - bb * nvis;
            int dst = g_vdst[bb][j];
            if (dst < 0) continue;
            float* orow = out + ((size_t)bb * L + dst) * DMODEL + nb0;
            #pragma unroll
            for (int nt = 0; nt < 4; nt++) {
                int col = wn * 32 + nt * 8 + qid * 2;
                float2 v;
                v.x = acc[mt][nt][half * 2 + 0] + sBias[col];
                v.y = acc[mt][nt][half * 2 + 1] + sBias[col + 1];
                __stcs(reinterpret_cast<float2*>(orow + col), v);
            }
        }
    }
}

// ---------------- host launch ----------------
extern "C" void kernel_launch(void* const* d_in, const int* in_sizes, int n_in,
                              void* d_out, int out_size) {
    const float* visual = (const float*)d_in[0];
    const float* emb    = (const float*)d_in[1];
    const float* Wp     = (const float*)d_in[2];
    const float* bp     = (const float*)d_in[3];
    const int*   texts  = (const int*)d_in[4];
    const int*   img_id = (const int*)d_in[5];

    const int D    = in_sizes[3];               // 1024
    const int DV   = in_sizes[2] / D;           // 1152
    const int nvis = in_sizes[0] / (NB * DV);   // 2304
    (void)n_in;

    double osB = (double)out_size / (double)NB;
    int L = (int)((-(double)DMODEL + sqrt((double)DMODEL * DMODEL + 4.0 * osB)) / 2.0 + 0.5);

    float* out_fused = (float*)d_out;
    float* out_mask  = (float*)d_out + (size_t)NB * L * DMODEL;
    const int Mtot = NB * nvis;  // 18432

    cudaFuncSetAttribute(gemm_h_kernel, cudaFuncAttributeMaxDynamicSharedMemorySize, GEMM_SMEM);

    plan_kernel<<<NB, 256>>>(texts, img_id, nvis, L);

    int n8 = Mtot * KDIM / 8;
    conv_a_kernel<<<(n8 + 255) / 256, 256>>>(visual, n8);

    prep_w_kernel<<<dim3(KDIM / 32, DMODEL / 32), dim3(32, 8)>>>(Wp);

    gather_kernel<<<(NB * L + 7) / 8, 256>>>(emb, texts, out_fused, L);

    dim3 mg((L + 1023) / 1024, (L + 15) / 16, NB);
    mask_kernel<<<mg, 256>>>(out_mask, L);

    gemm_h_kernel<<<dim3(DMODEL / GBN, Mtot / GBM), 256, GEMM_SMEM>>>(bp, out_fused, nvis, L);
}

// round 7
// speedup vs baseline: 1.9092x; 1.1363x over previous
#include <cuda_runtime.h>
#include <cuda_fp16.h>
#include <cstdint>
#include <math.h>

#define NB 8
#define SLEN 2048
#define DMODEL 1024
#define KDIM 1152
#define LMAX 4608
#define NVMAX 4608
#define MTOT (NB * 2304)   // 18432

// ---------------- device-global scratch (no allocs allowed) ----------------
__device__ int g_src[NB][LMAX];    // >=0: gather text pos; -2: visual (GEMM writes); -1: pad
__device__ int g_X[NB][LMAX];      // mask row r: ones for c < X_r, zeros after
__device__ int g_vdst[NB][NVMAX];  // visual token j -> fused row (or -1)
__device__ __half g_Ah[(size_t)MTOT * KDIM];     // visual features as fp16 (42.5MB)
__device__ __half g_Wh[(size_t)DMODEL * KDIM];   // W transposed to [N, K] fp16 (2.4MB)

// ---------------- PTX helpers ----------------
__device__ __forceinline__ uint32_t smem_u32(const void* p) {
    uint32_t a;
    asm("{ .reg .u64 t; cvta.to.shared.u64 t, %1; cvt.u32.u64 %0, t; }" : "=r"(a) : "l"(p));
    return a;
}
__device__ __forceinline__ void cp16(void* smem, const void* gmem) {
    uint32_t s = smem_u32(smem);
    asm volatile("cp.async.cg.shared.global [%0], [%1], 16;\n" :: "r"(s), "l"(gmem));
}
#define CP_COMMIT() asm volatile("cp.async.commit_group;\n")
#define CP_WAIT(n)  asm volatile("cp.async.wait_group %0;\n" :: "n"(n))

#define LDSM_X4(r, addr) \
    asm volatile("ldmatrix.sync.aligned.m8n8.x4.shared.b16 {%0,%1,%2,%3}, [%4];" \
        : "=r"((r)[0]), "=r"((r)[1]), "=r"((r)[2]), "=r"((r)[3]) : "r"(addr))

__device__ __forceinline__ void mma_f16(float* d, const uint32_t* a, const uint32_t* b) {
    asm volatile(
        "mma.sync.aligned.m16n8k16.row.col.f32.f16.f16.f32 "
        "{%0,%1,%2,%3}, {%4,%5,%6,%7}, {%8,%9}, {%0,%1,%2,%3};\n"
        : "+f"(d[0]), "+f"(d[1]), "+f"(d[2]), "+f"(d[3])
        : "r"(a[0]), "r"(a[1]), "r"(a[2]), "r"(a[3]), "r"(b[0]), "r"(b[1]));
}

// ---------------- plan: build interleave indices + mask prefix lengths -----
__global__ void plan_kernel(const int* __restrict__ texts,
                            const int* __restrict__ img_id_p,
                            int nvis, int L) {
    int b = blockIdx.x;
    int img_id = *img_id_p;
    const int* t = texts + b * SLEN;
    __shared__ int s_pos[64];
    __shared__ int s_n;
    if (threadIdx.x == 0) s_n = 0;
    __syncthreads();
    for (int p = threadIdx.x; p < SLEN; p += blockDim.x)
        if (t[p] == img_id) { int k = atomicAdd(&s_n, 1); if (k < 64) s_pos[k] = p; }
    __syncthreads();
    int n = min(s_n, 64);
    if (threadIdx.x == 0) {
        for (int i = 1; i < n; i++) {
            int v = s_pos[i]; int j = i - 1;
            while (j >= 0 && s_pos[j] > v) { s_pos[j + 1] = s_pos[j]; j--; }
            s_pos[j + 1] = v;
        }
    }
    __syncthreads();
    int per = (n > 0) ? (nvis / n) : 0;
    int len = (n > 0) ? (SLEN - n + n * per) : SLEN;
    // text tokens: causal within own chunk + all earlier -> prefix = fp+1
    for (int p = threadIdx.x; p < SLEN; p += blockDim.x) {
        if (t[p] == img_id) continue;
        int k = 0;
        while (k < n && s_pos[k] < p) k++;
        int fp = (p - k) + k * per;
        g_src[b][fp] = p;
        g_X[b][fp]   = fp + 1;
    }
    // visual tokens: bidirectional within chunk -> prefix = end of own chunk
    for (int j = threadIdx.x; j < nvis; j += blockDim.x) {
        int dst = -1;
        if (n > 0 && j < n * per) {
            int i = j / per;
            dst = (s_pos[i] - i) + i * per + (j - i * per);
            g_src[b][dst] = -2;
            g_X[b][dst]   = (s_pos[i] - i) + (i + 1) * per;
        }
        g_vdst[b][j] = dst;
    }
    // padding rows
    for (int l = len + threadIdx.x; l < L; l += blockDim.x) { g_src[b][l] = -1; g_X[b][l] = 0; }
}

// ---------------- convert A (visual) fp32 -> fp16 ----------------
__global__ void __launch_bounds__(256) conv_a_kernel(const float* __restrict__ A, int n8) {
    int i = blockIdx.x * 256 + threadIdx.x;
    if (i >= n8) return;
    const float4* src = reinterpret_cast<const float4*>(A) + (size_t)i * 2;
    float4 v0 = src[0], v1 = src[1];
    float4 o;
    o.x = __uint_as_float((uint32_t)__half_as_ushort(__float2half_rn(v0.x)) |
                          ((uint32_t)__half_as_ushort(__float2half_rn(v0.y)) << 16));
    o.y = __uint_as_float((uint32_t)__half_as_ushort(__float2half_rn(v0.z)) |
                          ((uint32_t)__half_as_ushort(__float2half_rn(v0.w)) << 16));
    o.z = __uint_as_float((uint32_t)__half_as_ushort(__float2half_rn(v1.x)) |
                          ((uint32_t)__half_as_ushort(__float2half_rn(v1.y)) << 16));
    o.w = __uint_as_float((uint32_t)__half_as_ushort(__float2half_rn(v1.z)) |
                          ((uint32_t)__half_as_ushort(__float2half_rn(v1.w)) << 16));
    __stcs(reinterpret_cast<float4*>(g_Ah) + i, o);
}

// ---------------- prep: transpose W -> g_Wh[N][K] fp16 ----------------
__global__ void __launch_bounds__(256) prep_w_kernel(const float* __restrict__ W) {
    __shared__ float t[32][33];
    int k0 = blockIdx.x * 32, n0 = blockIdx.y * 32;
    int tx = threadIdx.x & 31, ty = threadIdx.x >> 5;
    #pragma unroll
    for (int i = ty; i < 32; i += 8)
        t[i][tx] = W[(size_t)(k0 + i) * DMODEL + n0 + tx];
    __syncthreads();
    #pragma unroll
    for (int i = ty; i < 32; i += 8)
        g_Wh[(size_t)(n0 + i) * KDIM + k0 + tx] = __float2half_rn(t[tx][i]);
}

// ============ fused kernel: gemm + mask + gather, round-robin CTAs =========
#define GBM 128
#define GBN 128
#define GBK 32
#define STR_B 80                     // bytes per smem row (40 halves, ldmatrix conflict-free)
#define ATILE_B (128 * STR_B)        // 10240
#define STAGE_B (2 * ATILE_B)        // 20480
#define NSTG 4
#define GEMM_SMEM (NSTG * STAGE_B + 512)

__global__ void __launch_bounds__(256, 2) fused_kernel(
    const float* __restrict__ bias,
    const float* __restrict__ emb,
    const int*   __restrict__ texts,
    float* __restrict__ out_fused,
    float* __restrict__ out_mask,
    int nvis, int L, int nGemm, int nMask, int nGath, int mRowBlks)
{
    const int type = blockIdx.x % 3;
    const int sub  = blockIdx.x / 3;
    const int tid  = threadIdx.x;
    const int wid  = tid >> 5, lane = tid & 31;

    // ------------------------- type 1: mask blocks -------------------------
    if (type == 1) {
        if (sub >= nMask) return;
        __shared__ int sX[32];
        int b    = sub / mRowBlks;
        int r0   = (sub - b * mRowBlks) * 32;
        if (tid < 32) sX[tid] = (r0 + tid < L) ? g_X[b][r0 + tid] : 0;
        __syncthreads();
        int rmax = min(32, L - r0);
        int nChunks = (L + 1023) / 1024;
        for (int ch = 0; ch < nChunks; ch++) {
            int c = ch * 1024 + tid * 4;
            if (c >= L) break;  // L % 4 == 0
            size_t base = ((size_t)b * L + r0) * (size_t)L + c;
            #pragma unroll 4
            for (int i = 0; i < rmax; i++) {
                int X = sX[i];
                float4 v;
                v.x = (c + 0 < X) ? 1.f : 0.f;
                v.y = (c + 1 < X) ? 1.f : 0.f;
                v.z = (c + 2 < X) ? 1.f : 0.f;
                v.w = (c + 3 < X) ? 1.f : 0.f;
                __stcs(reinterpret_cast<float4*>(out_mask + base + (size_t)i * L), v);
            }
        }
        return;
    }

    // ------------------------ type 2: gather blocks ------------------------
    if (type == 2) {
        if (sub >= nGath) return;
        #pragma unroll
        for (int i = 0; i < 4; i++) {
            int row = sub * 32 + wid * 4 + i;
            if (row >= NB * L) break;
            int b = row / L, l = row - b * L;
            int src = g_src[b][l];
            if (src == -2) continue;  // visual row: GEMM epilogue writes it
            float4* dst = reinterpret_cast<float4*>(out_fused + ((size_t)b * L + l) * DMODEL);
            if (src < 0) {
                float4 z = make_float4(0.f, 0.f, 0.f, 0.f);
                #pragma unroll
                for (int k = 0; k < 8; k++) __stcs(dst + lane + k * 32, z);
                continue;
            }
            int tok = texts[b * SLEN + src];
            const float4* s = reinterpret_cast<const float4*>(emb + (size_t)tok * DMODEL);
            float4 v[8];
            #pragma unroll
            for (int k = 0; k < 8; k++) v[k] = s[lane + k * 32];
            #pragma unroll
            for (int k = 0; k < 8; k++) __stcs(dst + lane + k * 32, v[k]);
        }
        return;
    }

    // ------------------------- type 0: gemm blocks -------------------------
    if (sub >= nGemm) return;
    extern __shared__ char smem[];
    float* sBias = reinterpret_cast<float*>(smem + NSTG * STAGE_B);

    const int nb0 = (sub & 7) * GBN;        // 8 N-blocks (DMODEL/128)
    const int gm0 = (sub >> 3) * GBM;
    const int wm = wid & 1;       // 2 warps along M (64 rows)
    const int wn = wid >> 1;      // 4 warps along N (32 cols)
    const int grp = lane >> 2;
    const int qid = lane & 3;

    if (tid < 128) sBias[tid] = bias[nb0 + tid];

    const __half* Ag = g_Ah + (size_t)gm0 * KDIM;
    const __half* Bg = g_Wh + (size_t)nb0 * KDIM;

    float acc[4][4][4];
    #pragma unroll
    for (int i = 0; i < 4; i++)
        #pragma unroll
        for (int j = 0; j < 4; j++)
            #pragma unroll
            for (int k = 0; k < 4; k++) acc[i][j][k] = 0.f;

    const int KT = KDIM / GBK;  // 36

    auto issue = [&](int kt) {
        int s = kt % NSTG;
        char* dA = smem + s * STAGE_B;
        char* dB = dA + ATILE_B;
        #pragma unroll
        for (int v = tid; v < 512; v += 256) {
            int row = v >> 2, c = v & 3;
            cp16(dA + row * STR_B + c * 16, Ag + (size_t)row * KDIM + kt * GBK + c * 8);
        }
        #pragma unroll
        for (int v = tid; v < 512; v += 256) {
            int row = v >> 2, c = v & 3;
            cp16(dB + row * STR_B + c * 16, Bg + (size_t)row * KDIM + kt * GBK + c * 8);
        }
        CP_COMMIT();
    };

    issue(0);
    issue(1);
    issue(2);

    const int a_row = wm * 64 + (lane & 15);
    const int a_colb = (lane >> 4) * 16;
    const int b_row0 = wn * 32 + (lane & 7) + ((lane >> 4) & 1) * 8;
    const int b_colb = ((lane >> 3) & 1) * 16;

    for (int kt = 0; kt < KT; kt++) {
        // Tail-correct drain: guarantee group kt is complete before reading
        // stage kt%4. Pending set at this point is {kt .. min(kt+2, KT-1)}.
        if (kt <= KT - 3)      CP_WAIT(2);
        else if (kt == KT - 2) CP_WAIT(1);
        else                   CP_WAIT(0);
        __syncthreads();   // publish cp.async completions + order prior reads
        if (kt + 3 < KT) issue(kt + 3);

        char* sA = smem + (kt % NSTG) * STAGE_B;
        char* sB = sA + ATILE_B;
        #pragma unroll
        for (int ks = 0; ks < 2; ks++) {
            uint32_t a[4][4], bfr[2][4];
            #pragma unroll
            for (int mt = 0; mt < 4; mt++) {
                uint32_t addr = smem_u32(sA + (a_row + mt * 16) * STR_B + ks * 32 + a_colb);
                LDSM_X4(a[mt], addr);
            }
            #pragma unroll
            for (int p = 0; p < 2; p++) {
                uint32_t addr = smem_u32(sB + (b_row0 + p * 16) * STR_B + ks * 32 + b_colb);
                LDSM_X4(bfr[p], addr);
            }
            #pragma unroll
            for (int mt = 0; mt < 4; mt++) {
                #pragma unroll
                for (int nt = 0; nt < 4; nt++)
                    mma_f16(acc[mt][nt], a[mt], &bfr[nt >> 1][(nt & 1) * 2]);
            }
        }
    }

    // epilogue: scatter rows to fused positions
    #pragma unroll
    for (int mt = 0; mt < 4; mt++) {
        int gmA = gm0 + wm * 64 + mt * 16 + grp;
        #pragma unroll
        for (int half = 0; half < 2; half++) {
            int gm = gmA + half * 8;
            int bb = gm / nvis;
            int j  = gm - bb * nvis;
            int dst = g_vdst[bb][j];
            if (dst < 0) continue;
            float* orow = out_fused + ((size_t)bb * L + dst) * DMODEL + nb0;
            #pragma unroll
            for (int nt = 0; nt < 4; nt++) {
                int col = wn * 32 + nt * 8 + qid * 2;
                float2 v;
                v.x = acc[mt][nt][half * 2 + 0] + sBias[col];
                v.y = acc[mt][nt][half * 2 + 1] + sBias[col + 1];
                __stcs(reinterpret_cast<float2*>(orow + col), v);
            }
        }
    }
}

// ---------------- host launch ----------------
extern "C" void kernel_launch(void* const* d_in, const int* in_sizes, int n_in,
                              void* d_out, int out_size) {
    const float* visual = (const float*)d_in[0];
    const float* emb    = (const float*)d_in[1];
    const float* Wp     = (const float*)d_in[2];
    const float* bp     = (const float*)d_in[3];
    const int*   texts  = (const int*)d_in[4];
    const int*   img_id = (const int*)d_in[5];

    const int D    = in_sizes[3];               // 1024
    const int DV   = in_sizes[2] / D;           // 1152
    const int nvis = in_sizes[0] / (NB * DV);   // 2304
    (void)n_in;

    double osB = (double)out_size / (double)NB;
    int L = (int)((-(double)DMODEL + sqrt((double)DMODEL * DMODEL + 4.0 * osB)) / 2.0 + 0.5);

    float* out_fused = (float*)d_out;
    float* out_mask  = (float*)d_out + (size_t)NB * L * DMODEL;
    const int Mtot = NB * nvis;  // 18432

    const int nGemm    = (DMODEL / GBN) * (Mtot / GBM);  // 1152
    const int mRowBlks = (L + 31) / 32;                  // 136
    const int nMask    = NB * mRowBlks;                  // 1088
    const int nGath    = (NB * L + 31) / 32;             // 1087
    int gmax = nGemm;
    if (nMask > gmax) gmax = nMask;
    if (nGath > gmax) gmax = nGath;

    cudaFuncSetAttribute(fused_kernel, cudaFuncAttributeMaxDynamicSharedMemorySize, GEMM_SMEM);

    plan_kernel<<<NB, 256>>>(texts, img_id, nvis, L);

    int n8 = Mtot * KDIM / 8;
    conv_a_kernel<<<(n8 + 255) / 256, 256>>>(visual, n8);

    prep_w_kernel<<<dim3(KDIM / 32, DMODEL / 32), 256>>>(Wp);

    fused_kernel<<<3 * gmax, 256, GEMM_SMEM>>>(bp, emb, texts, out_fused, out_mask,
                                               nvis, L, nGemm, nMask, nGath, mRowBlks);
}